// round 8
// baseline (speedup 1.0000x reference)
#include <cuda_runtime.h>

// SPU transformer bound propagation: elementwise over N=8192 rows (320 KB total
// traffic) — overhead/latency-floor bound. Config: grid 32 x block 128,
// float4 = 2 rows/thread, MLP=4.
// Sigmoid branch via HW tanh: sigmoid(-x)-1 = -0.5 - 0.5*tanh(x/2)
// (one MUFU.TANH on the critical path instead of EX2->FADD->RCP).
// tanh.approx abs err ~1e-5 << 1e-3 threshold.

__device__ __forceinline__ float tanh_approx(float x) {
    float y;
    asm("tanh.approx.f32 %0, %1;" : "=f"(y) : "f"(x));
    return y;
}

__device__ __forceinline__ float spu_f(float x) {
    // x >= 0 : x*x - 0.5
    // x <  0 : sigmoid(-x) - 1 = -0.5 - 0.5*tanh(x/2)
    float p = fmaf(x, x, -0.5f);
    float t = tanh_approx(0.5f * x);
    float n = fmaf(-0.5f, t, -0.5f);
    return (x >= 0.0f) ? p : n;
}

__device__ __forceinline__ float2 spu_row(float l, float u,
                                          float ls_l, float ls_u,
                                          float lsh_l, float lsh_u,
                                          float lb_l, float lb_u) {
    float vl = spu_f(l);
    float vu = spu_f(u);

    bool neg   = (u <= 0.0f);
    bool pos   = (l >= 0.0f);
    bool cross = !(neg || pos);

    float all_slopes = __fdividef(vu - vl, u - l);
    float slope_u = (pos || cross) ? all_slopes : 0.0f;
    float slope_l = neg ? all_slopes : 0.0f;

    bool sw = (all_slopes < 0.0f);
    float v_l = sw ? vu : vl;
    float v_u = sw ? vl : vu;
    float b_l = sw ? u : l;
    float b_u = sw ? l : u;

    float bnd_l = cross ? -0.5f : v_l;
    float bnd_u = v_u;

    float shift_u = fmaf(-slope_u, b_u, v_u);
    float shift_l = cross ? -0.5f : fmaf(-slope_l, b_l, v_l);

    float Ud = slope_u * ls_u;
    float UV = fmaf(slope_u, lsh_u, shift_u);
    float Ld = slope_l * ls_l;
    float LV = fmaf(slope_l, lsh_l, shift_l);

    float lb = fmaf(fmaxf(Ld, 0.0f), lb_l, fmaf(fminf(Ld, 0.0f), lb_u, LV));
    float ub = fmaf(fmaxf(Ud, 0.0f), lb_u, fmaf(fminf(Ud, 0.0f), lb_l, UV));

    return make_float2(fmaxf(lb, bnd_l), fminf(ub, bnd_u));
}

__global__ void __launch_bounds__(128, 1) spu_transformer_kernel(
    const float4* __restrict__ bounds,
    const float4* __restrict__ last_slopes,
    const float4* __restrict__ last_shifts,
    const float4* __restrict__ last_bounds,
    float4* __restrict__ out,
    int n4)
{
    int i = blockIdx.x * blockDim.x + threadIdx.x;
    if (i < n4) {
        // 4 front-batched LDG.128 (MLP=4), straight-line math, one STG.128.
        float4 b   = bounds[i];
        float4 ls  = last_slopes[i];
        float4 lsh = last_shifts[i];
        float4 lb2 = last_bounds[i];

        float2 r0 = spu_row(b.x, b.y, ls.x, ls.y, lsh.x, lsh.y, lb2.x, lb2.y);
        float2 r1 = spu_row(b.z, b.w, ls.z, ls.w, lsh.z, lsh.w, lb2.z, lb2.w);

        out[i] = make_float4(r0.x, r0.y, r1.x, r1.y);
    }
}

extern "C" void kernel_launch(void* const* d_in, const int* in_sizes, int n_in,
                              void* d_out, int out_size) {
    const float4* bounds      = (const float4*)d_in[0];
    const float4* last_slopes = (const float4*)d_in[1];
    const float4* last_shifts = (const float4*)d_in[2];
    const float4* last_bounds = (const float4*)d_in[3];
    float4* out = (float4*)d_out;

    int n4 = in_sizes[0] / 4;            // 8192*2 floats -> 4096 float4
    const int threads = 128;
    int blocks = (n4 + threads - 1) / threads;  // 32
    spu_transformer_kernel<<<blocks, threads>>>(
        bounds, last_slopes, last_shifts, last_bounds, out, n4);
}